// round 8
// baseline (speedup 1.0000x reference)
#include <cuda_runtime.h>

typedef unsigned long long u64;

#define NSTEP 256   // C2
#define NTH   128   // threads per block; thread t owns complex elements 8t..8t+7
#define SGN   0x8000000080000000ULL

// Duplicated-broadcast coefficient store: [step][chunk 0..23][thread] float4,
// each float4 = two lane-duplicated u64s, directly usable by f32x2 ops.
//   rotA pair k (k=0..3):  chunk 3k   = (dr,dr,di,di)
//                          chunk 3k+1 = (or,or,oi,oi)
//                          chunk 3k+2 = (ct,ct,st,st)
//   rotB local k (k=0..2): chunk 12+3k..14+3k  same triplet
//   rotB boundary:         chunk 21 = (dr,dr,di,di), 22 = (or,or,oi,oi)
//   prev-pair (ct,st):     chunk 23 = (ct,ct,st,st) of pair 4t-1 (pre-shifted)
// 256*24*128*16B = 12.6 MB (L2-resident).
__device__ float4 gD[NSTEP * 24 * NTH];

__device__ __forceinline__ u64 pk(float lo, float hi) {
    u64 r; asm("mov.b64 %0, {%1, %2};" : "=l"(r) : "f"(lo), "f"(hi)); return r;
}
__device__ __forceinline__ void upk(u64 v, float& lo, float& hi) {
    asm("mov.b64 {%0, %1}, %2;" : "=f"(lo), "=f"(hi) : "l"(v));
}
__device__ __forceinline__ u64 mul2(u64 a, u64 b) {
    u64 r; asm("mul.rn.f32x2 %0, %1, %2;" : "=l"(r) : "l"(a), "l"(b)); return r;
}
__device__ __forceinline__ u64 fma2(u64 a, u64 b, u64 c) {
    u64 r; asm("fma.rn.f32x2 %0, %1, %2, %3;" : "=l"(r) : "l"(a), "l"(b), "l"(c)); return r;
}

// Full local pair rotation on 2 row-groups with pre-broadcast u64 coefficients.
__device__ __forceinline__ void rotpairD(u64* fr, u64* fi, u64* sr, u64* si,
                                         u64 dr, u64 di, u64 orr, u64 oi,
                                         u64 ct, u64 st) {
    u64 nd = di ^ SGN, no = oi ^ SGN;
#pragma unroll
    for (int g = 0; g < 2; g++) {
        u64 ar = mul2(dr, fr[g]); ar = fma2(nd, fi[g], ar);
        ar = fma2(orr, sr[g], ar); ar = fma2(no, si[g], ar);
        u64 ai = mul2(dr, fi[g]); ai = fma2(di, fr[g], ai);
        ai = fma2(orr, si[g], ai); ai = fma2(oi, sr[g], ai);
        u64 br = mul2(ct, sr[g]); br = fma2(st, fr[g], br);
        u64 bi = mul2(ct, si[g]); bi = fma2(st, fi[g], bi);
        fr[g] = ar; fi[g] = ai; sr[g] = br; si[g] = bi;
    }
}

// phi/theta arrays: (H2=512, C2=256) row-major -> [p*256 + c]
__global__ void coeff_kernel(const float* __restrict__ phi0, const float* __restrict__ th0,
                             const float* __restrict__ phi1, const float* __restrict__ th1) {
    int idx = blockIdx.x * blockDim.x + threadIdx.x;
    if (idx >= NSTEP * 512) return;
    int p = idx & 511;     // pair index
    int c = idx >> 9;      // step
    int t = p >> 2;        // owning eunn-thread (0..127)
    int k = p & 3;         // pair slot within thread
    int base = c * 24 * NTH;

    float sp, cp, st, ct;
    // Rotation A, pair p -> chunks 3k..3k+2
    sincosf(phi0[p * NSTEP + c], &sp, &cp);
    sincosf(th0[p * NSTEP + c], &st, &ct);
    {
        float dr = cp * ct, di = sp * ct, orr = -cp * st, oi = -sp * st;
        gD[base + (3 * k + 0) * NTH + t] = make_float4(dr, dr, di, di);
        gD[base + (3 * k + 1) * NTH + t] = make_float4(orr, orr, oi, oi);
        gD[base + (3 * k + 2) * NTH + t] = make_float4(ct, ct, st, st);
    }

    // Rotation B, pair p
    sincosf(phi1[p * NSTEP + c], &sp, &cp);
    sincosf(th1[p * NSTEP + c], &st, &ct);
    {
        float dr = cp * ct, di = sp * ct, orr = -cp * st, oi = -sp * st;
        if (k < 3) {
            gD[base + (12 + 3 * k + 0) * NTH + t] = make_float4(dr, dr, di, di);
            gD[base + (12 + 3 * k + 1) * NTH + t] = make_float4(orr, orr, oi, oi);
            gD[base + (12 + 3 * k + 2) * NTH + t] = make_float4(ct, ct, st, st);
        } else {
            gD[base + 21 * NTH + t] = make_float4(dr, dr, di, di);
            gD[base + 22 * NTH + t] = make_float4(orr, orr, oi, oi);
            // (ct,st) of pair 4t+3 consumed as "previous pair" by thread t+1 (mod 128)
            int ts = (t + 1) & (NTH - 1);
            gD[base + 23 * NTH + ts] = make_float4(ct, ct, st, st);
        }
    }
}

__global__ void __launch_bounds__(NTH, 4)
eunn_kernel(const float4* __restrict__ xin, float4* __restrict__ xout) {
    const int t    = threadIdx.x;
    const int lane = t & 31;
    const int w    = t >> 5;           // 4 warps
    const int row0 = blockIdx.x * 4;   // 4 batch rows per block (2 f32x2 groups)
    const ulonglong2* __restrict__ D = (const ulonglong2*)gD;

    u64 er[8][2], ei[8][2];
#pragma unroll
    for (int g = 0; g < 2; g++) {
        size_t r0 = (size_t)(row0 + 2 * g) * 512;
        size_t r1 = r0 + 512;
#pragma unroll
        for (int j = 0; j < 4; j++) {
            float4 a = xin[r0 + 4 * t + j];
            float4 b = xin[r1 + 4 * t + j];
            er[2 * j][g]     = pk(a.x, b.x); ei[2 * j][g]     = pk(a.y, b.y);
            er[2 * j + 1][g] = pk(a.z, b.z); ei[2 * j + 1][g] = pk(a.w, b.w);
        }
    }

    // Double-buffered warp-boundary exchange; one __syncthreads per step.
    __shared__ u64 sE0r[2][2][4], sE0i[2][2][4], sE7r[2][2][4], sE7i[2][2][4];

    for (int c = 0; c < NSTEP; c++) {
        const int base = c * 24 * NTH + t;

        // ---- Rotation A: pairs (e0,e1), (e2,e3), (e4,e5), (e6,e7) ----
        {
            ulonglong2 q0 = D[base + 0 * NTH], q1 = D[base + 1 * NTH], q2 = D[base + 2 * NTH];
            rotpairD(er[0], ei[0], er[1], ei[1], q0.x, q0.y, q1.x, q1.y, q2.x, q2.y);
        }
        {
            ulonglong2 q0 = D[base + 3 * NTH], q1 = D[base + 4 * NTH], q2 = D[base + 5 * NTH];
            rotpairD(er[2], ei[2], er[3], ei[3], q0.x, q0.y, q1.x, q1.y, q2.x, q2.y);
        }
        {
            ulonglong2 q0 = D[base + 6 * NTH], q1 = D[base + 7 * NTH], q2 = D[base + 8 * NTH];
            rotpairD(er[4], ei[4], er[5], ei[5], q0.x, q0.y, q1.x, q1.y, q2.x, q2.y);
        }
        {
            ulonglong2 q0 = D[base + 9 * NTH], q1 = D[base + 10 * NTH], q2 = D[base + 11 * NTH];
            rotpairD(er[6], ei[6], er[7], ei[7], q0.x, q0.y, q1.x, q1.y, q2.x, q2.y);
        }

        // Edge publish of post-A e0 / e7 (final values before boundary rotation)
        const int buf = c & 1;
        if (lane == 0) {
#pragma unroll
            for (int g = 0; g < 2; g++) { sE0r[buf][g][w] = er[0][g]; sE0i[buf][g][w] = ei[0][g]; }
        }
        if (lane == 31) {
#pragma unroll
            for (int g = 0; g < 2; g++) { sE7r[buf][g][w] = er[7][g]; sE7i[buf][g][w] = ei[7][g]; }
        }

        // Boundary SHFLs: sources final; issue early so latency is hidden
        u64 nbr[2], nbi[2], pvr[2], pvi[2];
#pragma unroll
        for (int g = 0; g < 2; g++) {
            nbr[g] = __shfl_down_sync(0xffffffffu, er[0][g], 1);
            nbi[g] = __shfl_down_sync(0xffffffffu, ei[0][g], 1);
            pvr[g] = __shfl_up_sync(0xffffffffu, er[7][g], 1);
            pvi[g] = __shfl_up_sync(0xffffffffu, ei[7][g], 1);
        }

        // ---- Rotation B, local pairs (e1,e2), (e3,e4), (e5,e6): pre-barrier ----
        {
            ulonglong2 q0 = D[base + 12 * NTH], q1 = D[base + 13 * NTH], q2 = D[base + 14 * NTH];
            rotpairD(er[1], ei[1], er[2], ei[2], q0.x, q0.y, q1.x, q1.y, q2.x, q2.y);
        }
        {
            ulonglong2 q0 = D[base + 15 * NTH], q1 = D[base + 16 * NTH], q2 = D[base + 17 * NTH];
            rotpairD(er[3], ei[3], er[4], ei[4], q0.x, q0.y, q1.x, q1.y, q2.x, q2.y);
        }
        {
            ulonglong2 q0 = D[base + 18 * NTH], q1 = D[base + 19 * NTH], q2 = D[base + 20 * NTH];
            rotpairD(er[5], ei[5], er[6], ei[6], q0.x, q0.y, q1.x, q1.y, q2.x, q2.y);
        }

        __syncthreads();

        // ---- Rotation B, boundary pair: (e7, next-thread e0) ----
        {
            ulonglong2 qd = D[base + 21 * NTH];   // (dr, di)
            ulonglong2 qo = D[base + 22 * NTH];   // (or, oi)
            ulonglong2 qp = D[base + 23 * NTH];   // (ct_prev, st_prev)
            u64 dr = qd.x, di = qd.y, orr = qo.x, oi = qo.y;
            u64 nd = di ^ SGN, no = oi ^ SGN, ctm = qp.x, stm = qp.y;
            const int wn = (w + 1) & 3, wp = (w + 3) & 3;
#pragma unroll
            for (int g = 0; g < 2; g++) {
                u64 xr = nbr[g], xi = nbi[g], yr = pvr[g], yi = pvi[g];
                if (lane == 31) { xr = sE0r[buf][g][wn]; xi = sE0i[buf][g][wn]; }
                if (lane == 0)  { yr = sE7r[buf][g][wp]; yi = sE7i[buf][g][wp]; }

                u64 cr = mul2(dr, er[7][g]); cr = fma2(nd, ei[7][g], cr);
                cr = fma2(orr, xr, cr);      cr = fma2(no, xi, cr);
                u64 ci = mul2(dr, ei[7][g]); ci = fma2(di, er[7][g], ci);
                ci = fma2(orr, xi, ci);      ci = fma2(oi, xr, ci);
                u64 zr = mul2(ctm, er[0][g]); zr = fma2(stm, yr, zr);
                u64 zi = mul2(ctm, ei[0][g]); zi = fma2(stm, yi, zi);
                er[7][g] = cr; ei[7][g] = ci; er[0][g] = zr; ei[0][g] = zi;
            }
        }
    }

#pragma unroll
    for (int g = 0; g < 2; g++) {
        size_t r0 = (size_t)(row0 + 2 * g) * 512;
        size_t r1 = r0 + 512;
#pragma unroll
        for (int j = 0; j < 4; j++) {
            float4 a, b;
            upk(er[2 * j][g], a.x, b.x);     upk(ei[2 * j][g], a.y, b.y);
            upk(er[2 * j + 1][g], a.z, b.z); upk(ei[2 * j + 1][g], a.w, b.w);
            xout[r0 + 4 * t + j] = a;
            xout[r1 + 4 * t + j] = b;
        }
    }
}

extern "C" void kernel_launch(void* const* d_in, const int* in_sizes, int n_in,
                              void* d_out, int out_size) {
    const float* x    = (const float*)d_in[0];
    const float* phi0 = (const float*)d_in[1];
    const float* th0  = (const float*)d_in[2];
    const float* phi1 = (const float*)d_in[3];
    const float* th1  = (const float*)d_in[4];

    coeff_kernel<<<(NSTEP * 512 + 255) / 256, 256>>>(phi0, th0, phi1, th1);
    eunn_kernel<<<4096 / 4, NTH>>>((const float4*)x, (float4*)d_out);
}